// round 2
// baseline (speedup 1.0000x reference)
#include <cuda_runtime.h>
#include <cuda_bf16.h>

#define N_NODES 50000
#define E_EDGES 800000
#define D_IN 128
#define D_H 96
#define D_OUT 32

// Scratch (allocation-free rule: __device__ globals)
__device__ float g_h1[N_NODES * D_H];     // x @ W1
__device__ float g_agg1[N_NODES * D_H];   // A @ h1 (atomic accum), relu applied on read
__device__ float g_h2[N_NODES * D_OUT];   // relu(agg1) @ W2

// ---------------------------------------------------------------------------
// GEMM1: h1 = x @ W1   [50000,128] @ [128,96]
// blockDim (96,4); W1 fully staged in DYNAMIC smem (48KB + 2KB > static cap).
// 32 rows per block.
// ---------------------------------------------------------------------------
#define GEMM1_SMEM ((D_IN * D_H + 4 * D_IN) * sizeof(float))

__global__ void gemm1_kernel(const float* __restrict__ x,
                             const float* __restrict__ W1) {
    extern __shared__ float smem[];
    float* sW = smem;                    // [D_IN * D_H]
    float* sx = smem + D_IN * D_H;       // [4][D_IN]

    int t = threadIdx.y * 96 + threadIdx.x;
    for (int i = t; i < D_IN * D_H; i += 384) sW[i] = W1[i];
    __syncthreads();

    const int ITER = 8;
    int baseRow = blockIdx.x * (4 * ITER);
    for (int r = 0; r < ITER; r++) {
        int row = baseRow + r * 4 + threadIdx.y;
        if (row < N_NODES) {
            sx[threadIdx.y * D_IN + threadIdx.x] = x[row * D_IN + threadIdx.x];
            if (threadIdx.x < 32)
                sx[threadIdx.y * D_IN + 96 + threadIdx.x] = x[row * D_IN + 96 + threadIdx.x];
        }
        __syncthreads();
        if (row < N_NODES) {
            float acc = 0.f;
#pragma unroll
            for (int k = 0; k < D_IN; k++)
                acc = fmaf(sx[threadIdx.y * D_IN + k], sW[k * D_H + threadIdx.x], acc);
            g_h1[row * D_H + threadIdx.x] = acc;
        }
        __syncthreads();
    }
}

// ---------------------------------------------------------------------------
// Zero kernels (agg1 atomic accumulator; d_out is poisoned by harness)
// ---------------------------------------------------------------------------
__global__ void zero_agg1_kernel() {
    int i = blockIdx.x * blockDim.x + threadIdx.x;
    int n4 = (N_NODES * D_H) / 4;
    if (i < n4) reinterpret_cast<float4*>(g_agg1)[i] = make_float4(0.f, 0.f, 0.f, 0.f);
}

__global__ void zero_out_kernel(float* out, int n) {
    int i = blockIdx.x * blockDim.x + threadIdx.x;
    if (i < n) out[i] = 0.f;
}

// ---------------------------------------------------------------------------
// SpMM1: agg1[dst] += val * h1[src], D_H=96 features.
// One warp per edge; lane handles feats {l, l+32, l+64}. Coalesced gather,
// atomic scatter (addresses mostly distinct -> L2 atomic ALU parallel).
// ---------------------------------------------------------------------------
__global__ void spmm96_kernel(const int* __restrict__ src,
                              const int* __restrict__ dst,
                              const float* __restrict__ val,
                              int n_edges) {
    int e = (blockIdx.x * blockDim.x + threadIdx.x) >> 5;
    if (e >= n_edges) return;
    int lane = threadIdx.x & 31;
    int s = src[e];
    int d = dst[e];
    float v = val[e];
    const float* hs = g_h1 + (long)s * D_H;
    float* od = g_agg1 + (long)d * D_H;
    atomicAdd(od + lane,      v * hs[lane]);
    atomicAdd(od + lane + 32, v * hs[lane + 32]);
    atomicAdd(od + lane + 64, v * hs[lane + 64]);
}

// ---------------------------------------------------------------------------
// GEMM2 (relu fused on input): h2 = relu(agg1) @ W2   [50000,96] @ [96,32]
// blockDim (32,8); W2 staged in smem (12KB + 3KB, static OK); 64 rows/block.
// ---------------------------------------------------------------------------
__global__ void gemm2_kernel(const float* __restrict__ W2) {
    __shared__ float sW[D_H * D_OUT];  // 12 KB
    __shared__ float sh[8][D_H];       // 3 KB

    int t = threadIdx.y * 32 + threadIdx.x;
    for (int i = t; i < D_H * D_OUT; i += 256) sW[i] = W2[i];
    __syncthreads();

    const int ITER = 8;
    int baseRow = blockIdx.x * (8 * ITER);
    for (int r = 0; r < ITER; r++) {
        int row = baseRow + r * 8 + threadIdx.y;
        if (row < N_NODES) {
#pragma unroll
            for (int j = 0; j < 3; j++) {
                float v = g_agg1[row * D_H + j * 32 + threadIdx.x];
                sh[threadIdx.y][j * 32 + threadIdx.x] = fmaxf(v, 0.f);
            }
        }
        __syncthreads();
        if (row < N_NODES) {
            float acc = 0.f;
#pragma unroll
            for (int k = 0; k < D_H; k++)
                acc = fmaf(sh[threadIdx.y][k], sW[k * D_OUT + threadIdx.x], acc);
            g_h2[row * D_OUT + threadIdx.x] = acc;
        }
        __syncthreads();
    }
}

// ---------------------------------------------------------------------------
// SpMM2: out[dst] += val * h2[src], D_OUT=32. One warp per edge, 1 feat/lane.
// ---------------------------------------------------------------------------
__global__ void spmm32_kernel(const int* __restrict__ src,
                              const int* __restrict__ dst,
                              const float* __restrict__ val,
                              float* __restrict__ out,
                              int n_edges) {
    int e = (blockIdx.x * blockDim.x + threadIdx.x) >> 5;
    if (e >= n_edges) return;
    int lane = threadIdx.x & 31;
    int s = src[e];
    int d = dst[e];
    float v = val[e];
    atomicAdd(out + (long)d * D_OUT + lane, v * g_h2[(long)s * D_OUT + lane]);
}

// ---------------------------------------------------------------------------
// Launch: gemm1 -> zero(agg1) -> spmm96 -> gemm2(relu fused) -> zero(out) -> spmm32
// All on default stream; graph-capturable; no allocation, no sync.
// ---------------------------------------------------------------------------
extern "C" void kernel_launch(void* const* d_in, const int* in_sizes, int n_in,
                              void* d_out, int out_size) {
    const float* x        = (const float*)d_in[0];
    const int*   edge_src = (const int*)  d_in[1];
    const int*   edge_dst = (const int*)  d_in[2];
    const float* edge_val = (const float*)d_in[3];
    const float* W1       = (const float*)d_in[4];
    const float* W2       = (const float*)d_in[5];
    float*       out      = (float*)d_out;

    int E = in_sizes[1];

    // Opt in to >48KB dynamic smem for gemm1 (idempotent, capture-safe).
    cudaFuncSetAttribute(gemm1_kernel,
                         cudaFuncAttributeMaxDynamicSharedMemorySize,
                         (int)GEMM1_SMEM);

    // GEMM1: 32 rows/block
    dim3 g1_block(96, 4);
    int  g1_grid = (N_NODES + 31) / 32;
    gemm1_kernel<<<g1_grid, g1_block, GEMM1_SMEM>>>(x, W1);

    // zero agg1 (float4)
    int zn = (N_NODES * D_H) / 4;
    zero_agg1_kernel<<<(zn + 255) / 256, 256>>>();

    // SpMM1: warp per edge
    long sp1_threads = (long)E * 32;
    spmm96_kernel<<<(int)((sp1_threads + 255) / 256), 256>>>(edge_src, edge_dst, edge_val, E);

    // GEMM2 with fused relu: 64 rows/block
    dim3 g2_block(32, 8);
    int  g2_grid = (N_NODES + 63) / 64;
    gemm2_kernel<<<g2_grid, g2_block>>>(W2);

    // zero d_out then SpMM2
    zero_out_kernel<<<(out_size + 255) / 256, 256>>>(out, out_size);
    long sp2_threads = (long)E * 32;
    spmm32_kernel<<<(int)((sp2_threads + 255) / 256), 256>>>(edge_src, edge_dst, edge_val, out, E);
}

// round 3
// speedup vs baseline: 1.6841x; 1.6841x over previous
#include <cuda_runtime.h>
#include <cuda_bf16.h>

#define N_NODES 50000
#define D_IN 128
#define D_H 96
#define D_OUT 32

// Scratch (allocation-free rule: __device__ globals)
__device__ float g_h1[N_NODES * D_H];     // x @ W1
__device__ float g_agg1[N_NODES * D_H];   // A @ h1 (atomic accum)
__device__ float g_h2[N_NODES * D_OUT];   // relu(agg1) @ W2

// ---------------------------------------------------------------------------
// GEMM1: h1 = x @ W1   [50000,128] @ [128,96]
// blockDim (96,4). Register tile: each thread computes 4 rows x 1 col.
// W1 transposed into smem (sWt[col][k], padded row 132), x tile 16 rows.
// float4 along k: per warp per 4-k: 1 W LDS.128 + 4 x LDS.128 (broadcast)
// + 16 FFMA -> FMA-pipe bound, 4 independent acc chains.
// ---------------------------------------------------------------------------
#define G1_PAD  132
#define G1_ROWS 16
#define G1_ITER 4
#define G1_SMEM ((D_H * G1_PAD + G1_ROWS * G1_PAD) * sizeof(float))

__global__ void gemm1_kernel(const float* __restrict__ x,
                             const float* __restrict__ W1) {
    extern __shared__ float smem[];
    float* sWt = smem;                    // [96][132]  (sWt[c][k] = W1[k][c])
    float* sx  = smem + D_H * G1_PAD;     // [16][132]

    const int tx = threadIdx.x, ty = threadIdx.y;
    const int t  = ty * 96 + tx;

    for (int i = t; i < D_IN * D_H; i += 384) {
        int k = i / D_H, c = i % D_H;
        sWt[c * G1_PAD + k] = W1[i];
    }
    __syncthreads();

    for (int it = 0; it < G1_ITER; it++) {
        int rowBase = (blockIdx.x * G1_ITER + it) * G1_ROWS;

        for (int i = t; i < G1_ROWS * D_IN; i += 384) {
            int r = i >> 7, k = i & 127;
            int row = rowBase + r;
            sx[r * G1_PAD + k] = (row < N_NODES) ? x[row * D_IN + k] : 0.f;
        }
        __syncthreads();

        float a0x=0,a0y=0,a0z=0,a0w=0;  // acc per row (kept as 4 scalars each? no: acc is scalar per row)
        float acc0=0.f, acc1=0.f, acc2=0.f, acc3=0.f;
        (void)a0x;(void)a0y;(void)a0z;(void)a0w;

        const float4* wrow = (const float4*)(sWt + tx * G1_PAD);
        const float4* xr0  = (const float4*)(sx + (ty * 4 + 0) * G1_PAD);
        const float4* xr1  = (const float4*)(sx + (ty * 4 + 1) * G1_PAD);
        const float4* xr2  = (const float4*)(sx + (ty * 4 + 2) * G1_PAD);
        const float4* xr3  = (const float4*)(sx + (ty * 4 + 3) * G1_PAD);

#pragma unroll
        for (int k4 = 0; k4 < D_IN / 4; k4++) {
            float4 w = wrow[k4];
            float4 v;
            v = xr0[k4]; acc0 = fmaf(v.x,w.x,fmaf(v.y,w.y,fmaf(v.z,w.z,fmaf(v.w,w.w,acc0))));
            v = xr1[k4]; acc1 = fmaf(v.x,w.x,fmaf(v.y,w.y,fmaf(v.z,w.z,fmaf(v.w,w.w,acc1))));
            v = xr2[k4]; acc2 = fmaf(v.x,w.x,fmaf(v.y,w.y,fmaf(v.z,w.z,fmaf(v.w,w.w,acc2))));
            v = xr3[k4]; acc3 = fmaf(v.x,w.x,fmaf(v.y,w.y,fmaf(v.z,w.z,fmaf(v.w,w.w,acc3))));
        }

        int r0 = rowBase + ty * 4;
        if (r0 + 0 < N_NODES) g_h1[(r0 + 0) * D_H + tx] = acc0;
        if (r0 + 1 < N_NODES) g_h1[(r0 + 1) * D_H + tx] = acc1;
        if (r0 + 2 < N_NODES) g_h1[(r0 + 2) * D_H + tx] = acc2;
        if (r0 + 3 < N_NODES) g_h1[(r0 + 3) * D_H + tx] = acc3;
        __syncthreads();
    }
}

// ---------------------------------------------------------------------------
// Zero kernels
// ---------------------------------------------------------------------------
__global__ void zero_agg1_kernel() {
    int i = blockIdx.x * blockDim.x + threadIdx.x;
    int n4 = (N_NODES * D_H) / 4;
    if (i < n4) reinterpret_cast<float4*>(g_agg1)[i] = make_float4(0.f, 0.f, 0.f, 0.f);
}

__global__ void zero_out_kernel(float* out, int n) {
    int i = blockIdx.x * blockDim.x + threadIdx.x;
    if (i < n) out[i] = 0.f;
}

// ---------------------------------------------------------------------------
// SpMM1: agg1[dst] += val * h1[src], D_H=96.
// One thread per (edge, 4-float chunk): 24 chunks/edge. float4 gather,
// red.global.add.v4.f32 scatter -> 4x fewer L2 atomic ops than scalar.
// ---------------------------------------------------------------------------
__global__ void spmm96_kernel(const int* __restrict__ src,
                              const int* __restrict__ dst,
                              const float* __restrict__ val,
                              int n_edges) {
    int idx = blockIdx.x * blockDim.x + threadIdx.x;
    int e = idx / 24;
    if (e >= n_edges) return;
    int c = idx - e * 24;
    int s = __ldg(src + e);
    int d = __ldg(dst + e);
    float v = __ldg(val + e);
    float4 h = *reinterpret_cast<const float4*>(g_h1 + (long)s * D_H + c * 4);
    float* p = g_agg1 + (long)d * D_H + c * 4;
    asm volatile("red.global.add.v4.f32 [%0], {%1, %2, %3, %4};"
                 :: "l"(p), "f"(v * h.x), "f"(v * h.y), "f"(v * h.z), "f"(v * h.w)
                 : "memory");
}

// ---------------------------------------------------------------------------
// GEMM2 (relu fused on input): h2 = relu(agg1) @ W2   [50000,96] @ [96,32]
// blockDim (32,8). Same register-tiling scheme as gemm1: 4 rows/thread.
// ---------------------------------------------------------------------------
#define G2_PAD  100
#define G2_ROWS 32
#define G2_ITER 2

__global__ void gemm2_kernel(const float* __restrict__ W2) {
    __shared__ float sWt[D_OUT * G2_PAD];   // [32][100] transposed, 12.8KB
    __shared__ float sh[G2_ROWS * G2_PAD];  // [32][100], 12.8KB

    const int tx = threadIdx.x, ty = threadIdx.y;
    const int t  = ty * 32 + tx;

    for (int i = t; i < D_H * D_OUT; i += 256) {
        int k = i / D_OUT, c = i % D_OUT;
        sWt[c * G2_PAD + k] = W2[i];
    }
    __syncthreads();

    for (int it = 0; it < G2_ITER; it++) {
        int rowBase = (blockIdx.x * G2_ITER + it) * G2_ROWS;

        for (int i = t; i < G2_ROWS * D_H; i += 256) {
            int r = i / D_H, k = i - r * D_H;
            int row = rowBase + r;
            float v = (row < N_NODES) ? g_agg1[row * D_H + k] : 0.f;
            sh[r * G2_PAD + k] = fmaxf(v, 0.f);
        }
        __syncthreads();

        float acc0=0.f, acc1=0.f, acc2=0.f, acc3=0.f;
        const float4* wrow = (const float4*)(sWt + tx * G2_PAD);
        const float4* xr0  = (const float4*)(sh + (ty * 4 + 0) * G2_PAD);
        const float4* xr1  = (const float4*)(sh + (ty * 4 + 1) * G2_PAD);
        const float4* xr2  = (const float4*)(sh + (ty * 4 + 2) * G2_PAD);
        const float4* xr3  = (const float4*)(sh + (ty * 4 + 3) * G2_PAD);

#pragma unroll
        for (int k4 = 0; k4 < D_H / 4; k4++) {
            float4 w = wrow[k4];
            float4 v;
            v = xr0[k4]; acc0 = fmaf(v.x,w.x,fmaf(v.y,w.y,fmaf(v.z,w.z,fmaf(v.w,w.w,acc0))));
            v = xr1[k4]; acc1 = fmaf(v.x,w.x,fmaf(v.y,w.y,fmaf(v.z,w.z,fmaf(v.w,w.w,acc1))));
            v = xr2[k4]; acc2 = fmaf(v.x,w.x,fmaf(v.y,w.y,fmaf(v.z,w.z,fmaf(v.w,w.w,acc2))));
            v = xr3[k4]; acc3 = fmaf(v.x,w.x,fmaf(v.y,w.y,fmaf(v.z,w.z,fmaf(v.w,w.w,acc3))));
        }

        int r0 = rowBase + ty * 4;
        if (r0 + 0 < N_NODES) g_h2[(r0 + 0) * D_OUT + tx] = acc0;
        if (r0 + 1 < N_NODES) g_h2[(r0 + 1) * D_OUT + tx] = acc1;
        if (r0 + 2 < N_NODES) g_h2[(r0 + 2) * D_OUT + tx] = acc2;
        if (r0 + 3 < N_NODES) g_h2[(r0 + 3) * D_OUT + tx] = acc3;
        __syncthreads();
    }
}

// ---------------------------------------------------------------------------
// SpMM2: out[dst] += val * h2[src], D_OUT=32. 8 threads/edge, float4 each.
// ---------------------------------------------------------------------------
__global__ void spmm32_kernel(const int* __restrict__ src,
                              const int* __restrict__ dst,
                              const float* __restrict__ val,
                              float* __restrict__ out,
                              int n_edges) {
    int idx = blockIdx.x * blockDim.x + threadIdx.x;
    int e = idx >> 3;
    if (e >= n_edges) return;
    int c = idx & 7;
    int s = __ldg(src + e);
    int d = __ldg(dst + e);
    float v = __ldg(val + e);
    float4 h = *reinterpret_cast<const float4*>(g_h2 + (long)s * D_OUT + c * 4);
    float* p = out + (long)d * D_OUT + c * 4;
    asm volatile("red.global.add.v4.f32 [%0], {%1, %2, %3, %4};"
                 :: "l"(p), "f"(v * h.x), "f"(v * h.y), "f"(v * h.z), "f"(v * h.w)
                 : "memory");
}

// ---------------------------------------------------------------------------
// Launch: gemm1 -> zero(agg1) -> spmm96 -> gemm2 -> zero(out) -> spmm32
// ---------------------------------------------------------------------------
extern "C" void kernel_launch(void* const* d_in, const int* in_sizes, int n_in,
                              void* d_out, int out_size) {
    const float* x        = (const float*)d_in[0];
    const int*   edge_src = (const int*)  d_in[1];
    const int*   edge_dst = (const int*)  d_in[2];
    const float* edge_val = (const float*)d_in[3];
    const float* W1       = (const float*)d_in[4];
    const float* W2       = (const float*)d_in[5];
    float*       out      = (float*)d_out;

    int E = in_sizes[1];

    cudaFuncSetAttribute(gemm1_kernel,
                         cudaFuncAttributeMaxDynamicSharedMemorySize,
                         (int)G1_SMEM);

    // GEMM1: 16 rows/iter, 4 iters -> 64 rows/block
    dim3 g1_block(96, 4);
    int  g1_grid = (N_NODES + G1_ROWS * G1_ITER - 1) / (G1_ROWS * G1_ITER);
    gemm1_kernel<<<g1_grid, g1_block, G1_SMEM>>>(x, W1);

    int zn = (N_NODES * D_H) / 4;
    zero_agg1_kernel<<<(zn + 255) / 256, 256>>>();

    // SpMM1: 24 threads/edge (float4 chunks)
    long sp1_threads = (long)E * 24;
    spmm96_kernel<<<(int)((sp1_threads + 255) / 256), 256>>>(edge_src, edge_dst, edge_val, E);

    // GEMM2: 32 rows/iter, 2 iters -> 64 rows/block
    dim3 g2_block(32, 8);
    int  g2_grid = (N_NODES + G2_ROWS * G2_ITER - 1) / (G2_ROWS * G2_ITER);
    gemm2_kernel<<<g2_grid, g2_block>>>(W2);

    zero_out_kernel<<<(out_size + 255) / 256, 256>>>(out, out_size);

    // SpMM2: 8 threads/edge (float4 chunks)
    long sp2_threads = (long)E * 8;
    spmm32_kernel<<<(int)((sp2_threads + 255) / 256), 256>>>(edge_src, edge_dst, edge_val, out, E);
}